// round 16
// baseline (speedup 1.0000x reference)
#include <cuda_runtime.h>
#include <cuda_bf16.h>
#include <cstdint>
#include <cstddef>

#define TA      262144      // T*A = 2048*128
#define D_OBS   64
#define NTP     4
#define HDIM    64
#define NA      16
#define OUTC    17
#define TILE    256
#define NTHR    256
#define NCTA    148         // persistent, 1/SM (255-reg budget)
#define ECTAS   18          // per expert (4*18=72), critic gets 76

#define WTS     36          // WT[n][kp] stride (u32); 144B rows -> ldmatrix conflict-free

typedef unsigned long long u64;

// ---------------- scratch ----------------
__device__ int g_perm[NTP * TA];
__device__ int g_cnt[NTP];
__device__ int g_flag;

// ---------------- helpers ----------------
__device__ __forceinline__ uint32_t smem_u32(const void* p) {
    uint32_t a;
    asm("{ .reg .u64 t; cvta.to.shared.u64 t, %1; cvt.u32.u64 %0, t; }" : "=r"(a) : "l"(p));
    return a;
}
__device__ __forceinline__ uint32_t cvt_bf2(float lo, float hi) {
    uint32_t r;
    asm("cvt.rn.bf16x2.f32 %0, %1, %2;" : "=r"(r) : "f"(hi), "f"(lo));
    return r;
}
__device__ __forceinline__ void split2(float v0, float v1, uint32_t& uh, uint32_t& ul) {
    uh = cvt_bf2(v0, v1);
    float r0 = v0 - __uint_as_float(uh << 16);
    float r1 = v1 - __uint_as_float(uh & 0xffff0000u);
    ul = cvt_bf2(r0, r1);
}

#define MMA_BF16(c, a, b0, b1) \
    asm volatile("mma.sync.aligned.m16n8k16.row.col.f32.bf16.bf16.f32 " \
        "{%0,%1,%2,%3},{%4,%5,%6,%7},{%8,%9},{%0,%1,%2,%3};" \
        : "+f"((c)[0]), "+f"((c)[1]), "+f"((c)[2]), "+f"((c)[3]) \
        : "r"((a)[0]), "r"((a)[1]), "r"((a)[2]), "r"((a)[3]), "r"(b0), "r"(b1))

#define LDSM4(r, addr) \
    asm volatile("ldmatrix.sync.aligned.m8n8.x4.shared.b16 {%0,%1,%2,%3}, [%4];" \
        : "=r"((r)[0]), "=r"((r)[1]), "=r"((r)[2]), "=r"((r)[3]) : "r"(addr))

// ---------------- prologue kernels ----------------
__global__ void k_init() {
    int t = threadIdx.x;
    if (t < NTP) g_cnt[t] = 0;
    if (t == NTP) g_flag = 0;
}
__global__ void k_detect(const int* __restrict__ h) {
    int stride = gridDim.x * blockDim.x;
    int acc = 0;
    for (int j = blockIdx.x * blockDim.x + threadIdx.x; j < TA / 2; j += stride)
        acc |= h[2 * j + 1];
    unsigned any = __ballot_sync(0xffffffffu, acc != 0);
    if ((threadIdx.x & 31) == 0 && any) atomicOr(&g_flag, 1);
}
__device__ __forceinline__ int pick_at(const int* __restrict__ h, int i, int f) {
    return f ? h[i] : h[2 * i];
}
__global__ void k_build(const int* __restrict__ h) {
    __shared__ int sHist[NTP], sBase[NTP], sRank[NTP];
    int tid = threadIdx.x;
    if (tid < NTP) { sHist[tid] = 0; sRank[tid] = 0; }
    __syncthreads();
    int f = g_flag;
    int i = blockIdx.x * 512 + tid;
    int t = pick_at(h, i, f);
    atomicAdd(&sHist[t], 1);
    __syncthreads();
    if (tid < NTP) sBase[tid] = atomicAdd(&g_cnt[tid], sHist[tid]);
    __syncthreads();
    int p = atomicAdd(&sRank[t], 1);
    g_perm[t * TA + sBase[t] + p] = i;
}

// ---------------- smem layout (u32 indices): weights/biases only ----------------
#define U_B1   0                          // 64
#define U_W1G  64                         // 256
#define U_B2   320                        // 64
#define U_B3   384                        // 32
#define U_VW   416                        // 64
#define U_W1H  480                        // 64*36 = 2304
#define U_W1L  (U_W1H + 2304)
#define U_W2H  (U_W1L + 2304)
#define U_W2L  (U_W2H + 2304)
#define U_W3H  (U_W2L + 2304)             // 16*36 = 576
#define U_W3L  (U_W3H + 576)
#define SMEM_U32 (U_W3L + 576)
#define SMEM_BYTES (SMEM_U32 * 4)         // ~43 KB

#define BSTEP  (16 * WTS * 4)             // B n-group byte step

__global__ void __launch_bounds__(NTHR, 1) mlp_hmma(
    const float* __restrict__ obs, const float* __restrict__ gp,
    const float* __restrict__ W1, const float* __restrict__ b1,
    const float* __restrict__ W2, const float* __restrict__ b2,
    const float* __restrict__ W3, const float* __restrict__ b3,
    const float* __restrict__ cW1, const float* __restrict__ cb1,
    const float* __restrict__ cW2, const float* __restrict__ cb2,
    const float* __restrict__ cW3, const float* __restrict__ cb3,
    float* __restrict__ out) {
    extern __shared__ uint32_t su[];
    float* sB1 = (float*)(su + U_B1);
    float* sW1G = (float*)(su + U_W1G);
    float* sB2 = (float*)(su + U_B2);
    float* sB3 = (float*)(su + U_B3);
    float* sVW = (float*)(su + U_VW);

    const int tid = threadIdx.x;
    const int lane = tid & 31;
    const int w = tid >> 5;
    const int cta = blockIdx.x;
    const bool critic = (cta >= NTP * ECTAS);

    int e = 0, j0, tstride, ntiles, cnt;
    if (!critic) {
        e = cta / ECTAS;
        j0 = cta - e * ECTAS;
        tstride = ECTAS;
        cnt = g_cnt[e];
        ntiles = (cnt + TILE - 1) / TILE;
    } else {
        j0 = cta - NTP * ECTAS;
        tstride = NCTA - NTP * ECTAS;   // 76
        cnt = TA;
        ntiles = TA / TILE;             // 1024
    }

    // ---- stage weights once: WT[n][kp] pair-packed bf16 hi/lo (K=64) ----
    {
        const float* w1 = critic ? cW1 : (W1 + (size_t)e * 68 * HDIM);
        for (int i = tid; i < 64 * 32; i += NTHR) {
            int n = i >> 5, kp = i & 31;
            uint32_t h, l;
            split2(w1[(2 * kp) * 64 + n], w1[(2 * kp + 1) * 64 + n], h, l);
            su[U_W1H + n * WTS + kp] = h;
            su[U_W1L + n * WTS + kp] = l;
        }
        if (tid < 256) sW1G[tid] = w1[64 * 64 + tid];
        const float* w2 = critic ? cW2 : (W2 + (size_t)e * HDIM * HDIM);
        for (int i = tid; i < 64 * 32; i += NTHR) {
            int n = i >> 5, kp = i & 31;
            uint32_t h, l;
            split2(w2[(2 * kp) * 64 + n], w2[(2 * kp + 1) * 64 + n], h, l);
            su[U_W2H + n * WTS + kp] = h;
            su[U_W2L + n * WTS + kp] = l;
        }
        if (!critic) {
            const float* w3 = W3 + (size_t)e * HDIM * NA;
            for (int i = tid; i < 16 * 32; i += NTHR) {
                int n = i >> 5, kp = i & 31;
                uint32_t h, l;
                split2(w3[(2 * kp) * 16 + n], w3[(2 * kp + 1) * 16 + n], h, l);
                su[U_W3H + n * WTS + kp] = h;
                su[U_W3L + n * WTS + kp] = l;
            }
            if (tid < HDIM) { sB1[tid] = b1[e * HDIM + tid]; sB2[tid] = b2[e * HDIM + tid]; }
            if (tid < NA) sB3[tid] = b3[e * NA + tid];
        } else {
            if (tid < HDIM) { sB1[tid] = cb1[tid]; sB2[tid] = cb2[tid]; sVW[tid] = cW3[tid]; }
            if (tid < NA) sB3[tid] = (tid == 0) ? cb3[0] : 0.0f;
        }
    }
    __syncthreads();   // weights visible; the ONLY barrier

    const int* permBase = g_perm + (critic ? 0 : e * TA);
    const int m0 = w * 32;               // warp-private 32-row band (2 m16 groups)
    const int lr = lane >> 2, lq = lane & 3;

    // ---- ldmatrix per-lane byte addresses (B only) ----
    const uint32_t sb = smem_u32(su);
    const int mat = lane >> 3, lrow = lane & 7;
    const uint32_t bLane = 4 * (((mat >> 1) * 8 + lrow) * WTS + (mat & 1) * 4);
    const uint32_t b1H = sb + 4 * U_W1H + bLane;
    const uint32_t b1L = b1H + 4 * (U_W1L - U_W1H);
    const uint32_t b2H = sb + 4 * U_W2H + bLane;
    const uint32_t b2L = b2H + 4 * (U_W2L - U_W2H);
    const uint32_t b3H = sb + 4 * U_W3H + bLane;
    const uint32_t b3L = b3H + 4 * (U_W3L - U_W3H);

    for (int t = j0; t < ntiles; t += tstride) {
        const int start = t * TILE;
        const int nvalid = min(TILE, cnt - start);

        // ---- per-thread rows: gi=0..3 -> tile row m0 + gi*8 + lr ----
        int rowg[4];
        const float* xp[4];
#pragma unroll
        for (int gi = 0; gi < 4; gi++) {
            int r = m0 + gi * 8 + lr;
            int row;
            if (critic) row = start + r;
            else row = (r < nvalid) ? permBase[start + r] : permBase[start];
            rowg[gi] = row;
            xp[gi] = obs + (size_t)row * D_OBS;
        }

        // ---- layer 1: A fragments straight from gmem, B shared by 2 groups ----
        float C1[2][8][4];
#pragma unroll
        for (int g = 0; g < 2; g++)
#pragma unroll
            for (int nt = 0; nt < 8; nt++)
#pragma unroll
                for (int i = 0; i < 4; i++) C1[g][nt][i] = 0.0f;
#pragma unroll
        for (int ks = 0; ks < 4; ks++) {
            int k0 = ks * 16 + 2 * lq;
            uint32_t ah[2][4], al[2][4];
#pragma unroll
            for (int g = 0; g < 2; g++) {
                float2 xa = *(const float2*)(xp[2 * g] + k0);
                float2 xb = *(const float2*)(xp[2 * g + 1] + k0);
                float2 xc = *(const float2*)(xp[2 * g] + k0 + 8);
                float2 xd = *(const float2*)(xp[2 * g + 1] + k0 + 8);
                split2(xa.x, xa.y, ah[g][0], al[g][0]);
                split2(xb.x, xb.y, ah[g][1], al[g][1]);
                split2(xc.x, xc.y, ah[g][2], al[g][2]);
                split2(xd.x, xd.y, ah[g][3], al[g][3]);
            }
#pragma unroll
            for (int gg = 0; gg < 2; gg++) {
                uint32_t bh[2][4], bl[2][4];
                LDSM4(bh[0], b1H + (2 * gg) * BSTEP + ks * 32);
                LDSM4(bh[1], b1H + (2 * gg + 1) * BSTEP + ks * 32);
                LDSM4(bl[0], b1L + (2 * gg) * BSTEP + ks * 32);
                LDSM4(bl[1], b1L + (2 * gg + 1) * BSTEP + ks * 32);
#pragma unroll
                for (int q = 0; q < 4; q++) {
                    int nt = gg * 4 + q, gq = q >> 1, s = (q & 1) * 2;
#pragma unroll
                    for (int g = 0; g < 2; g++) {
                        MMA_BF16(C1[g][nt], ah[g], bh[gq][s], bh[gq][s + 1]);
                        MMA_BF16(C1[g][nt], al[g], bh[gq][s], bh[gq][s + 1]);
                        MMA_BF16(C1[g][nt], ah[g], bl[gq][s], bl[gq][s + 1]);
                    }
                }
            }
        }

        // ---- epi1 (registers): bias(+gp fold) + relu + split -> A fragments ----
        uint32_t Fh[2][8][2], Fl[2][8][2];
        {
            float4 gv[4];
#pragma unroll
            for (int gi = 0; gi < 4; gi++)
                gv[gi] = *(const float4*)(gp + (size_t)(rowg[gi] >> 7) * NTP);
#pragma unroll
            for (int nt = 0; nt < 8; nt++) {
                int n = nt * 8 + lq * 2;
                float w00 = sW1G[n],       w01 = sW1G[64 + n],
                      w02 = sW1G[128 + n], w03 = sW1G[192 + n];
                float w10 = sW1G[n + 1],       w11 = sW1G[64 + n + 1],
                      w12 = sW1G[128 + n + 1], w13 = sW1G[192 + n + 1];
                float b0 = sB1[n], b1v = sB1[n + 1];
#pragma unroll
                for (int g = 0; g < 2; g++) {
                    float4 ga = gv[2 * g], gb = gv[2 * g + 1];
                    float ba0 = b0 + ga.x * w00 + ga.y * w01 + ga.z * w02 + ga.w * w03;
                    float ba1 = b1v + ga.x * w10 + ga.y * w11 + ga.z * w12 + ga.w * w13;
                    float bb0 = b0 + gb.x * w00 + gb.y * w01 + gb.z * w02 + gb.w * w03;
                    float bb1 = b1v + gb.x * w10 + gb.y * w11 + gb.z * w12 + gb.w * w13;
                    float v0 = fmaxf(C1[g][nt][0] + ba0, 0.0f);
                    float v1 = fmaxf(C1[g][nt][1] + ba1, 0.0f);
                    split2(v0, v1, Fh[g][nt][0], Fl[g][nt][0]);
                    v0 = fmaxf(C1[g][nt][2] + bb0, 0.0f);
                    v1 = fmaxf(C1[g][nt][3] + bb1, 0.0f);
                    split2(v0, v1, Fh[g][nt][1], Fl[g][nt][1]);
                }
            }
        }

        // ---- layer 2: A entirely from registers, B shared by 2 groups ----
        float C2[2][8][4];
#pragma unroll
        for (int g = 0; g < 2; g++)
#pragma unroll
            for (int nt = 0; nt < 8; nt++)
#pragma unroll
                for (int i = 0; i < 4; i++) C2[g][nt][i] = 0.0f;
#pragma unroll
        for (int j = 0; j < 4; j++) {
#pragma unroll
            for (int gg = 0; gg < 2; gg++) {
                uint32_t bh[2][4], bl[2][4];
                LDSM4(bh[0], b2H + (2 * gg) * BSTEP + j * 32);
                LDSM4(bh[1], b2H + (2 * gg + 1) * BSTEP + j * 32);
                LDSM4(bl[0], b2L + (2 * gg) * BSTEP + j * 32);
                LDSM4(bl[1], b2L + (2 * gg + 1) * BSTEP + j * 32);
#pragma unroll
                for (int g = 0; g < 2; g++) {
                    uint32_t ah[4] = {Fh[g][2 * j][0], Fh[g][2 * j][1],
                                      Fh[g][2 * j + 1][0], Fh[g][2 * j + 1][1]};
                    uint32_t al[4] = {Fl[g][2 * j][0], Fl[g][2 * j][1],
                                      Fl[g][2 * j + 1][0], Fl[g][2 * j + 1][1]};
#pragma unroll
                    for (int q = 0; q < 4; q++) {
                        int nt = gg * 4 + q, gq = q >> 1, s = (q & 1) * 2;
                        MMA_BF16(C2[g][nt], ah, bh[gq][s], bh[gq][s + 1]);
                        MMA_BF16(C2[g][nt], al, bh[gq][s], bh[gq][s + 1]);
                        MMA_BF16(C2[g][nt], ah, bl[gq][s], bl[gq][s + 1]);
                    }
                }
            }
        }

        // ---- H2 = relu(C2 + b2) in registers ----
#pragma unroll
        for (int nt = 0; nt < 8; nt++) {
            int n = nt * 8 + lq * 2;
            float bb0 = sB2[n], bb1 = sB2[n + 1];
#pragma unroll
            for (int g = 0; g < 2; g++) {
                C2[g][nt][0] = fmaxf(C2[g][nt][0] + bb0, 0.0f);
                C2[g][nt][1] = fmaxf(C2[g][nt][1] + bb1, 0.0f);
                C2[g][nt][2] = fmaxf(C2[g][nt][2] + bb0, 0.0f);
                C2[g][nt][3] = fmaxf(C2[g][nt][3] + bb1, 0.0f);
            }
        }

        if (!critic) {
            // ---- layer 3 fully fused: A from registers, B shared ----
            float C3[2][2][4];
#pragma unroll
            for (int g = 0; g < 2; g++)
#pragma unroll
                for (int nt3 = 0; nt3 < 2; nt3++)
#pragma unroll
                    for (int i = 0; i < 4; i++) C3[g][nt3][i] = 0.0f;
#pragma unroll
            for (int j = 0; j < 4; j++) {
                uint32_t bh[4], bl[4];
                LDSM4(bh, b3H + j * 32);
                LDSM4(bl, b3L + j * 32);
#pragma unroll
                for (int g = 0; g < 2; g++) {
                    uint32_t ah[4], al[4];
                    split2(C2[g][2 * j][0], C2[g][2 * j][1], ah[0], al[0]);
                    split2(C2[g][2 * j][2], C2[g][2 * j][3], ah[1], al[1]);
                    split2(C2[g][2 * j + 1][0], C2[g][2 * j + 1][1], ah[2], al[2]);
                    split2(C2[g][2 * j + 1][2], C2[g][2 * j + 1][3], ah[3], al[3]);
#pragma unroll
                    for (int nt3 = 0; nt3 < 2; nt3++) {
                        int s = nt3 * 2;
                        MMA_BF16(C3[g][nt3], ah, bh[s], bh[s + 1]);
                        MMA_BF16(C3[g][nt3], al, bh[s], bh[s + 1]);
                        MMA_BF16(C3[g][nt3], ah, bl[s], bl[s + 1]);
                    }
                }
            }
#pragma unroll
            for (int g = 0; g < 2; g++) {
                int ra = m0 + 16 * g + lr, rb = ra + 8;
#pragma unroll
                for (int nt3 = 0; nt3 < 2; nt3++) {
                    int n = nt3 * 8 + lq * 2;
                    float b0 = sB3[n], b1v = sB3[n + 1];
                    if (ra < nvalid) {
                        size_t o = (size_t)rowg[2 * g] * OUTC + n;
                        out[o] = C3[g][nt3][0] + b0;
                        out[o + 1] = C3[g][nt3][1] + b1v;
                    }
                    if (rb < nvalid) {
                        size_t o = (size_t)rowg[2 * g + 1] * OUTC + n;
                        out[o] = C3[g][nt3][2] + b0;
                        out[o + 1] = C3[g][nt3][3] + b1v;
                    }
                }
            }
        } else {
            // ---- critic: value = H2 . cW3 fully in registers ----
#pragma unroll
            for (int g = 0; g < 2; g++) {
                float v0 = 0.0f, v1 = 0.0f;
#pragma unroll
                for (int nt = 0; nt < 8; nt++) {
                    int n = nt * 8 + lq * 2;
                    float w0 = sVW[n], w1v = sVW[n + 1];
                    v0 += C2[g][nt][0] * w0 + C2[g][nt][1] * w1v;
                    v1 += C2[g][nt][2] * w0 + C2[g][nt][3] * w1v;
                }
                v0 += __shfl_xor_sync(0xffffffffu, v0, 1);
                v0 += __shfl_xor_sync(0xffffffffu, v0, 2);
                v1 += __shfl_xor_sync(0xffffffffu, v1, 1);
                v1 += __shfl_xor_sync(0xffffffffu, v1, 2);
                if (lq == 0) {
                    float vb = sB3[0];
                    out[(size_t)rowg[2 * g] * OUTC + NA] = v0 + vb;
                    out[(size_t)rowg[2 * g + 1] * OUTC + NA] = v1 + vb;
                }
            }
        }
    }
}

// ---------------- launch ----------------
extern "C" void kernel_launch(void* const* d_in, const int* in_sizes, int n_in,
                              void* d_out, int out_size) {
    const float* obs  = (const float*)d_in[0];
    const int*   hete = (const int*)d_in[1];
    const float* gp   = (const float*)d_in[2];
    const float* W1   = (const float*)d_in[3];
    const float* b1   = (const float*)d_in[4];
    const float* W2   = (const float*)d_in[5];
    const float* b2   = (const float*)d_in[6];
    const float* W3   = (const float*)d_in[7];
    const float* b3   = (const float*)d_in[8];
    const float* cW1  = (const float*)d_in[9];
    const float* cb1  = (const float*)d_in[10];
    const float* cW2  = (const float*)d_in[11];
    const float* cb2  = (const float*)d_in[12];
    const float* cW3  = (const float*)d_in[13];
    const float* cb3  = (const float*)d_in[14];
    float* out = (float*)d_out;

    cudaFuncSetAttribute(mlp_hmma, cudaFuncAttributeMaxDynamicSharedMemorySize,
                         SMEM_BYTES);

    k_init<<<1, 32>>>();
    k_detect<<<128, 256>>>(hete);
    k_build<<<TA / 512, 512>>>(hete);

    mlp_hmma<<<NCTA, NTHR, SMEM_BYTES>>>(obs, gp, W1, b1, W2, b2, W3, b3,
                                         cW1, cb1, cW2, cb2, cW3, cb3, out);
}

// round 17
// speedup vs baseline: 1.4013x; 1.4013x over previous
#include <cuda_runtime.h>
#include <cuda_fp16.h>
#include <cstdint>
#include <cstddef>

#define TA      262144      // T*A = 2048*128
#define D_OBS   64
#define NTP     4
#define HDIM    64
#define NA      16
#define OUTC    17
#define TILE    128
#define NTHR    256
#define NCTA    296         // persistent, 2/SM
#define ECTAS   37          // per expert (4*37=148), critic gets 148

#define WTS     36          // WT[n][kp] stride (u32); 144B rows -> ldmatrix conflict-free

typedef unsigned long long u64;

// ---------------- scratch ----------------
__device__ int g_perm[NTP * TA];
__device__ int g_cnt[NTP];
__device__ int g_flag;

// ---------------- helpers ----------------
__device__ __forceinline__ uint32_t smem_u32(const void* p) {
    uint32_t a;
    asm("{ .reg .u64 t; cvta.to.shared.u64 t, %1; cvt.u32.u64 %0, t; }" : "=r"(a) : "l"(p));
    return a;
}
// pack f16x2: low half = f16(lo), high half = f16(hi)
__device__ __forceinline__ uint32_t cvt_h2(float lo, float hi) {
    uint32_t r;
    asm("cvt.rn.f16x2.f32 %0, %1, %2;" : "=r"(r) : "f"(hi), "f"(lo));
    return r;
}
// fp16 2-way split: v = hi + lo with hi = f16(v), lo = f16(v - hi)
__device__ __forceinline__ void split2h(float v0, float v1, uint32_t& uh, uint32_t& ul) {
    uh = cvt_h2(v0, v1);
    float f0, f1;
    asm("{ .reg .b16 a, b; mov.b32 {a, b}, %2; cvt.f32.f16 %0, a; cvt.f32.f16 %1, b; }"
        : "=f"(f0), "=f"(f1) : "r"(uh));
    ul = cvt_h2(v0 - f0, v1 - f1);
}

#define MMA_F16(c, a, b0, b1) \
    asm volatile("mma.sync.aligned.m16n8k16.row.col.f32.f16.f16.f32 " \
        "{%0,%1,%2,%3},{%4,%5,%6,%7},{%8,%9},{%0,%1,%2,%3};" \
        : "+f"((c)[0]), "+f"((c)[1]), "+f"((c)[2]), "+f"((c)[3]) \
        : "r"((a)[0]), "r"((a)[1]), "r"((a)[2]), "r"((a)[3]), "r"(b0), "r"(b1))

#define LDSM4(r, addr) \
    asm volatile("ldmatrix.sync.aligned.m8n8.x4.shared.b16 {%0,%1,%2,%3}, [%4];" \
        : "=r"((r)[0]), "=r"((r)[1]), "=r"((r)[2]), "=r"((r)[3]) : "r"(addr))

// ---------------- prologue kernels ----------------
__global__ void k_init() {
    int t = threadIdx.x;
    if (t < NTP) g_cnt[t] = 0;
    if (t == NTP) g_flag = 0;
}
__global__ void k_detect(const int* __restrict__ h) {
    int stride = gridDim.x * blockDim.x;
    int acc = 0;
    for (int j = blockIdx.x * blockDim.x + threadIdx.x; j < TA / 2; j += stride)
        acc |= h[2 * j + 1];
    unsigned any = __ballot_sync(0xffffffffu, acc != 0);
    if ((threadIdx.x & 31) == 0 && any) atomicOr(&g_flag, 1);
}
__device__ __forceinline__ int pick_at(const int* __restrict__ h, int i, int f) {
    return f ? h[i] : h[2 * i];
}
__global__ void k_build(const int* __restrict__ h) {
    __shared__ int sHist[NTP], sBase[NTP], sRank[NTP];
    int tid = threadIdx.x;
    if (tid < NTP) { sHist[tid] = 0; sRank[tid] = 0; }
    __syncthreads();
    int f = g_flag;
    int i = blockIdx.x * 512 + tid;
    int t = pick_at(h, i, f);
    atomicAdd(&sHist[t], 1);
    __syncthreads();
    if (tid < NTP) sBase[tid] = atomicAdd(&g_cnt[tid], sHist[tid]);
    __syncthreads();
    int p = atomicAdd(&sRank[t], 1);
    g_perm[t * TA + sBase[t] + p] = i;
}

// ---------------- smem layout (u32 indices): weights/biases only ----------------
#define U_B1   0                          // 64
#define U_W1G  64                         // 256
#define U_B2   320                        // 64
#define U_B3   384                        // 32
#define U_VW   416                        // 64
#define U_W1   480                        // 64*36 = 2304
#define U_W2   (U_W1 + 2304)
#define U_W3   (U_W2 + 2304)              // 16*36 = 576
#define SMEM_U32 (U_W3 + 576)
#define SMEM_BYTES (SMEM_U32 * 4)         // ~23 KB

#define BSTEP  (16 * WTS * 4)             // B n-group byte step

__global__ void __launch_bounds__(NTHR, 2) mlp_hmma(
    const float* __restrict__ obs, const float* __restrict__ gp,
    const float* __restrict__ W1, const float* __restrict__ b1,
    const float* __restrict__ W2, const float* __restrict__ b2,
    const float* __restrict__ W3, const float* __restrict__ b3,
    const float* __restrict__ cW1, const float* __restrict__ cb1,
    const float* __restrict__ cW2, const float* __restrict__ cb2,
    const float* __restrict__ cW3, const float* __restrict__ cb3,
    float* __restrict__ out) {
    extern __shared__ uint32_t su[];
    float* sB1 = (float*)(su + U_B1);
    float* sW1G = (float*)(su + U_W1G);
    float* sB2 = (float*)(su + U_B2);
    float* sB3 = (float*)(su + U_B3);
    float* sVW = (float*)(su + U_VW);

    const int tid = threadIdx.x;
    const int lane = tid & 31;
    const int w = tid >> 5;
    const int cta = blockIdx.x;
    const bool critic = (cta >= NTP * ECTAS);

    int e = 0, j0, tstride, ntiles, cnt;
    if (!critic) {
        e = cta / ECTAS;
        j0 = cta - e * ECTAS;
        tstride = ECTAS;
        cnt = g_cnt[e];
        ntiles = (cnt + TILE - 1) / TILE;
    } else {
        j0 = cta - NTP * ECTAS;
        tstride = NCTA - NTP * ECTAS;   // 148
        cnt = TA;
        ntiles = TA / TILE;
    }

    // ---- stage weights once: WT[n][kp] f16x2 over k-pairs (single precision level) ----
    {
        const float* w1 = critic ? cW1 : (W1 + (size_t)e * 68 * HDIM);
        for (int i = tid; i < 64 * 32; i += NTHR) {
            int n = i >> 5, kp = i & 31;
            su[U_W1 + n * WTS + kp] = cvt_h2(w1[(2 * kp) * 64 + n], w1[(2 * kp + 1) * 64 + n]);
        }
        if (tid < 256) sW1G[tid] = w1[64 * 64 + tid];
        const float* w2 = critic ? cW2 : (W2 + (size_t)e * HDIM * HDIM);
        for (int i = tid; i < 64 * 32; i += NTHR) {
            int n = i >> 5, kp = i & 31;
            su[U_W2 + n * WTS + kp] = cvt_h2(w2[(2 * kp) * 64 + n], w2[(2 * kp + 1) * 64 + n]);
        }
        if (!critic) {
            const float* w3 = W3 + (size_t)e * HDIM * NA;
            for (int i = tid; i < 16 * 32; i += NTHR) {
                int n = i >> 5, kp = i & 31;
                su[U_W3 + n * WTS + kp] = cvt_h2(w3[(2 * kp) * 16 + n], w3[(2 * kp + 1) * 16 + n]);
            }
            if (tid < HDIM) { sB1[tid] = b1[e * HDIM + tid]; sB2[tid] = b2[e * HDIM + tid]; }
            if (tid < NA) sB3[tid] = b3[e * NA + tid];
        } else {
            if (tid < HDIM) { sB1[tid] = cb1[tid]; sB2[tid] = cb2[tid]; sVW[tid] = cW3[tid]; }
            if (tid < NA) sB3[tid] = (tid == 0) ? cb3[0] : 0.0f;
        }
    }
    __syncthreads();   // weights visible; the ONLY barrier

    const int* permBase = g_perm + (critic ? 0 : e * TA);
    const int m0 = w * 16;               // warp-private 16-row band
    const int lr = lane >> 2, lq = lane & 3;

    // ---- ldmatrix per-lane byte addresses (B only) ----
    const uint32_t sb = smem_u32(su);
    const int mat = lane >> 3, lrow = lane & 7;
    const uint32_t bLane = 4 * (((mat >> 1) * 8 + lrow) * WTS + (mat & 1) * 4);
    const uint32_t b1B = sb + 4 * U_W1 + bLane;
    const uint32_t b2B = sb + 4 * U_W2 + bLane;
    const uint32_t b3B = sb + 4 * U_W3 + bLane;

    for (int t = j0; t < ntiles; t += tstride) {
        const int start = t * TILE;
        const int nvalid = min(TILE, cnt - start);

        // ---- per-thread rows (fragment partition: rows m0+lr, m0+lr+8) ----
        int r0 = m0 + lr, r1 = r0 + 8;
        int row0, row1;
        if (critic) { row0 = start + r0; row1 = start + r1; }
        else {
            row0 = (r0 < nvalid) ? permBase[start + r0] : permBase[start];
            row1 = (r1 < nvalid) ? permBase[start + r1] : permBase[start];
        }
        const float* x0 = obs + (size_t)row0 * D_OBS;
        const float* x1 = obs + (size_t)row1 * D_OBS;

        // ---- layer 1: A (fp16 hi/lo) straight from gmem, B single fp16 ----
        float C1[8][4];
#pragma unroll
        for (int nt = 0; nt < 8; nt++)
#pragma unroll
            for (int i = 0; i < 4; i++) C1[nt][i] = 0.0f;
#pragma unroll
        for (int ks = 0; ks < 4; ks++) {
            int k0 = ks * 16 + 2 * lq;
            float2 xa = *(const float2*)(x0 + k0);
            float2 xb = *(const float2*)(x1 + k0);
            float2 xc = *(const float2*)(x0 + k0 + 8);
            float2 xd = *(const float2*)(x1 + k0 + 8);
            uint32_t ah[4], al[4];
            split2h(xa.x, xa.y, ah[0], al[0]);
            split2h(xb.x, xb.y, ah[1], al[1]);
            split2h(xc.x, xc.y, ah[2], al[2]);
            split2h(xd.x, xd.y, ah[3], al[3]);
#pragma unroll
            for (int gg = 0; gg < 2; gg++) {
                uint32_t bb[2][4];
                LDSM4(bb[0], b1B + (2 * gg) * BSTEP + ks * 32);
                LDSM4(bb[1], b1B + (2 * gg + 1) * BSTEP + ks * 32);
#pragma unroll
                for (int q = 0; q < 4; q++) {
                    int nt = gg * 4 + q, g = q >> 1, s = (q & 1) * 2;
                    MMA_F16(C1[nt], ah, bb[g][s], bb[g][s + 1]);
                    MMA_F16(C1[nt], al, bb[g][s], bb[g][s + 1]);
                }
            }
        }

        // ---- epi1 (registers): bias(+gp fold from gmem) + relu + split ----
        uint32_t Fh[8][2], Fl[8][2];
        {
            float4 ga = *(const float4*)(gp + (size_t)(row0 >> 7) * NTP);
            float4 gb = *(const float4*)(gp + (size_t)(row1 >> 7) * NTP);
#pragma unroll
            for (int nt = 0; nt < 8; nt++) {
                int n = nt * 8 + lq * 2;
                float w00 = sW1G[n],       w01 = sW1G[64 + n],
                      w02 = sW1G[128 + n], w03 = sW1G[192 + n];
                float w10 = sW1G[n + 1],       w11 = sW1G[64 + n + 1],
                      w12 = sW1G[128 + n + 1], w13 = sW1G[192 + n + 1];
                float b0 = sB1[n], b1v = sB1[n + 1];
                float ba0 = b0 + ga.x * w00 + ga.y * w01 + ga.z * w02 + ga.w * w03;
                float ba1 = b1v + ga.x * w10 + ga.y * w11 + ga.z * w12 + ga.w * w13;
                float bb0 = b0 + gb.x * w00 + gb.y * w01 + gb.z * w02 + gb.w * w03;
                float bb1 = b1v + gb.x * w10 + gb.y * w11 + gb.z * w12 + gb.w * w13;
                float v0 = fmaxf(C1[nt][0] + ba0, 0.0f);
                float v1 = fmaxf(C1[nt][1] + ba1, 0.0f);
                split2h(v0, v1, Fh[nt][0], Fl[nt][0]);
                v0 = fmaxf(C1[nt][2] + bb0, 0.0f);
                v1 = fmaxf(C1[nt][3] + bb1, 0.0f);
                split2h(v0, v1, Fh[nt][1], Fl[nt][1]);
            }
        }

        // ---- layer 2: A entirely from registers ----
        float C2[8][4];
#pragma unroll
        for (int nt = 0; nt < 8; nt++)
#pragma unroll
            for (int i = 0; i < 4; i++) C2[nt][i] = 0.0f;
#pragma unroll
        for (int j = 0; j < 4; j++) {
            uint32_t ah[4] = {Fh[2 * j][0], Fh[2 * j][1], Fh[2 * j + 1][0], Fh[2 * j + 1][1]};
            uint32_t al[4] = {Fl[2 * j][0], Fl[2 * j][1], Fl[2 * j + 1][0], Fl[2 * j + 1][1]};
#pragma unroll
            for (int gg = 0; gg < 2; gg++) {
                uint32_t bb[2][4];
                LDSM4(bb[0], b2B + (2 * gg) * BSTEP + j * 32);
                LDSM4(bb[1], b2B + (2 * gg + 1) * BSTEP + j * 32);
#pragma unroll
                for (int q = 0; q < 4; q++) {
                    int nt = gg * 4 + q, g = q >> 1, s = (q & 1) * 2;
                    MMA_F16(C2[nt], ah, bb[g][s], bb[g][s + 1]);
                    MMA_F16(C2[nt], al, bb[g][s], bb[g][s + 1]);
                }
            }
        }

        // ---- H2 = relu(C2 + b2) in registers ----
#pragma unroll
        for (int nt = 0; nt < 8; nt++) {
            int n = nt * 8 + lq * 2;
            float bb0 = sB2[n], bb1 = sB2[n + 1];
            C2[nt][0] = fmaxf(C2[nt][0] + bb0, 0.0f);
            C2[nt][1] = fmaxf(C2[nt][1] + bb1, 0.0f);
            C2[nt][2] = fmaxf(C2[nt][2] + bb0, 0.0f);
            C2[nt][3] = fmaxf(C2[nt][3] + bb1, 0.0f);
        }

        if (!critic) {
            // ---- layer 3 fully fused: A from registers ----
            float C3[2][4];
#pragma unroll
            for (int nt3 = 0; nt3 < 2; nt3++)
#pragma unroll
                for (int i = 0; i < 4; i++) C3[nt3][i] = 0.0f;
#pragma unroll
            for (int j = 0; j < 4; j++) {
                uint32_t bb[4];
                LDSM4(bb, b3B + j * 32);
                uint32_t ah[4], al[4];
                split2h(C2[2 * j][0], C2[2 * j][1], ah[0], al[0]);
                split2h(C2[2 * j][2], C2[2 * j][3], ah[1], al[1]);
                split2h(C2[2 * j + 1][0], C2[2 * j + 1][1], ah[2], al[2]);
                split2h(C2[2 * j + 1][2], C2[2 * j + 1][3], ah[3], al[3]);
#pragma unroll
                for (int nt3 = 0; nt3 < 2; nt3++) {
                    int s = nt3 * 2;
                    MMA_F16(C3[nt3], ah, bb[s], bb[s + 1]);
                    MMA_F16(C3[nt3], al, bb[s], bb[s + 1]);
                }
            }
#pragma unroll
            for (int nt3 = 0; nt3 < 2; nt3++) {
                int n = nt3 * 8 + lq * 2;
                float b0 = sB3[n], b1v = sB3[n + 1];
                if (r0 < nvalid) {
                    size_t o = (size_t)row0 * OUTC + n;
                    out[o] = C3[nt3][0] + b0;
                    out[o + 1] = C3[nt3][1] + b1v;
                }
                if (r1 < nvalid) {
                    size_t o = (size_t)row1 * OUTC + n;
                    out[o] = C3[nt3][2] + b0;
                    out[o + 1] = C3[nt3][3] + b1v;
                }
            }
        } else {
            // ---- critic: value = H2 . cW3 fully in registers (fp32) ----
            float v0 = 0.0f, v1 = 0.0f;
#pragma unroll
            for (int nt = 0; nt < 8; nt++) {
                int n = nt * 8 + lq * 2;
                float w0 = sVW[n], w1v = sVW[n + 1];
                v0 += C2[nt][0] * w0 + C2[nt][1] * w1v;
                v1 += C2[nt][2] * w0 + C2[nt][3] * w1v;
            }
            v0 += __shfl_xor_sync(0xffffffffu, v0, 1);
            v0 += __shfl_xor_sync(0xffffffffu, v0, 2);
            v1 += __shfl_xor_sync(0xffffffffu, v1, 1);
            v1 += __shfl_xor_sync(0xffffffffu, v1, 2);
            if (lq == 0) {
                float vb = sB3[0];
                out[(size_t)row0 * OUTC + NA] = v0 + vb;
                out[(size_t)row1 * OUTC + NA] = v1 + vb;
            }
        }
    }
}

// ---------------- launch ----------------
extern "C" void kernel_launch(void* const* d_in, const int* in_sizes, int n_in,
                              void* d_out, int out_size) {
    const float* obs  = (const float*)d_in[0];
    const int*   hete = (const int*)d_in[1];
    const float* gp   = (const float*)d_in[2];
    const float* W1   = (const float*)d_in[3];
    const float* b1   = (const float*)d_in[4];
    const float* W2   = (const float*)d_in[5];
    const float* b2   = (const float*)d_in[6];
    const float* W3   = (const float*)d_in[7];
    const float* b3   = (const float*)d_in[8];
    const float* cW1  = (const float*)d_in[9];
    const float* cb1  = (const float*)d_in[10];
    const float* cW2  = (const float*)d_in[11];
    const float* cb2  = (const float*)d_in[12];
    const float* cW3  = (const float*)d_in[13];
    const float* cb3  = (const float*)d_in[14];
    float* out = (float*)d_out;

    cudaFuncSetAttribute(mlp_hmma, cudaFuncAttributeMaxDynamicSharedMemorySize,
                         SMEM_BYTES);

    k_init<<<1, 32>>>();
    k_detect<<<128, 256>>>(hete);
    k_build<<<TA / 512, 512>>>(hete);

    mlp_hmma<<<NCTA, NTHR, SMEM_BYTES>>>(obs, gp, W1, b1, W2, b2, W3, b3,
                                         cW1, cb1, cW2, cb2, cW3, cb3, out);
}